// round 17
// baseline (speedup 1.0000x reference)
#include <cuda_runtime.h>
#include <math.h>

#define NH   16
#define DH   64
#define DM   1024
#define BB   2
#define LQ   2048
#define LK   2048
#define MTOT (BB*LQ)
#define NT   (LK/64)

// Head-major projected scratch: [(b*NH+h), L, DH]
__device__ float g_Qh[BB*NH*LQ*DH];
__device__ float g_Kh[BB*NH*LK*DH];
__device__ float g_Vh[BB*NH*LK*DH];

__device__ __forceinline__ unsigned f2tf(float f) {
    unsigned r;
    asm("cvt.rna.tf32.f32 %0, %1;" : "=r"(r) : "f"(f));
    return r;
}

__device__ __forceinline__ void mma_tf32(float* d, const unsigned* a, const unsigned* b) {
    asm volatile(
        "mma.sync.aligned.m16n8k8.row.col.f32.tf32.tf32.f32 "
        "{%0,%1,%2,%3}, {%4,%5,%6,%7}, {%8,%9}, {%0,%1,%2,%3};"
        : "+f"(d[0]), "+f"(d[1]), "+f"(d[2]), "+f"(d[3])
        : "r"(a[0]), "r"(a[1]), "r"(a[2]), "r"(a[3]), "r"(b[0]), "r"(b[1]));
}

// ---------------------------------------------------------------------------
// Projection: R10-verified single-buffer form + 2 CTAs/SM via launch_bounds.
// BM=BN=128, BK=32, 256 threads, tf32 warp-mma, head-major out.
// ---------------------------------------------------------------------------
#define PST 36

__global__ __launch_bounds__(256, 2) void proj_kernel(
    const float* __restrict__ q, const float* __restrict__ k, const float* __restrict__ v,
    const float* __restrict__ Wq, const float* __restrict__ bq,
    const float* __restrict__ Wk, const float* __restrict__ bk,
    const float* __restrict__ Wv, const float* __restrict__ bv)
{
    const float *A, *W, *bias;
    float* out;
    if (blockIdx.z == 0)      { A = q; W = Wq; bias = bq; out = g_Qh; }
    else if (blockIdx.z == 1) { A = k; W = Wk; bias = bk; out = g_Kh; }
    else                      { A = v; W = Wv; bias = bv; out = g_Vh; }

    __shared__ unsigned As[128 * PST];
    __shared__ unsigned Ws[128 * PST];

    const int tid  = threadIdx.x;
    const int warp = tid >> 5, lane = tid & 31;
    const int g = lane >> 2, tg = lane & 3;
    const int wm = warp >> 2;
    const int wn = warp & 3;
    const int m0 = blockIdx.y * 128;
    const int n0 = blockIdx.x * 128;

    float acc[4][4][4];
#pragma unroll
    for (int mt = 0; mt < 4; mt++)
#pragma unroll
        for (int nt = 0; nt < 4; nt++)
#pragma unroll
            for (int i = 0; i < 4; i++) acc[mt][nt][i] = 0.f;

    const int lrow = tid >> 3;      // 0..31
    const int lc4  = tid & 7;

    for (int k0 = 0; k0 < DM; k0 += 32) {
        __syncthreads();
#pragma unroll
        for (int rep = 0; rep < 4; rep++) {
            int row = lrow + rep * 32;
            float4 av = *(const float4*)(A + (size_t)(m0 + row) * DM + k0 + lc4 * 4);
            *(uint4*)&As[row * PST + lc4 * 4] =
                make_uint4(f2tf(av.x), f2tf(av.y), f2tf(av.z), f2tf(av.w));
            float4 wv = *(const float4*)(W + (size_t)(n0 + row) * DM + k0 + lc4 * 4);
            *(uint4*)&Ws[row * PST + lc4 * 4] =
                make_uint4(f2tf(wv.x), f2tf(wv.y), f2tf(wv.z), f2tf(wv.w));
        }
        __syncthreads();

#pragma unroll
        for (int kk = 0; kk < 4; kk++) {
            unsigned a[4][4], b[4][2];
#pragma unroll
            for (int mt = 0; mt < 4; mt++) {
                int base = (wm * 64 + mt * 16 + g) * PST + kk * 8 + tg;
                a[mt][0] = As[base];
                a[mt][1] = As[base + 8 * PST];
                a[mt][2] = As[base + 4];
                a[mt][3] = As[base + 8 * PST + 4];
            }
#pragma unroll
            for (int nt = 0; nt < 4; nt++) {
                int base = (wn * 32 + nt * 8 + g) * PST + kk * 8 + tg;
                b[nt][0] = Ws[base];
                b[nt][1] = Ws[base + 4];
            }
#pragma unroll
            for (int mt = 0; mt < 4; mt++)
#pragma unroll
                for (int nt = 0; nt < 4; nt++)
                    mma_tf32(acc[mt][nt], a[mt], b[nt]);
        }
    }

#pragma unroll
    for (int nt = 0; nt < 4; nt++) {
        int n = n0 + wn * 32 + nt * 8 + 2 * tg;
        int h = n >> 6, d = n & 63;
        float2 bb = *(const float2*)(bias + n);
#pragma unroll
        for (int mt = 0; mt < 4; mt++) {
            int m = m0 + wm * 64 + mt * 16 + g;
            int b_ = m >> 11, r = m & (LQ - 1);
            float* p0 = out + (((size_t)b_ * NH + h) * LQ + r) * DH + d;
            *(float2*)p0 = make_float2(acc[mt][nt][0] + bb.x, acc[mt][nt][1] + bb.y);
            float* p1 = out + (((size_t)b_ * NH + h) * LQ + (r + 8)) * DH + d;
            *(float2*)p1 = make_float2(acc[mt][nt][2] + bb.x, acc[mt][nt][3] + bb.y);
        }
    }
}

// ---------------------------------------------------------------------------
// Pipelined attention (unchanged from measured 513us version). 512 threads.
// S-side (warps 0-7): stage K-frags, S=QK^T, softmax, publish P+alpha (tile t)
// O-side (warps 8-11: O_v rows o*32..+31; warps 12-15: O_k): tile t-1,
//   B-fragments shared across two row-tiles (one LDS.64 feeds two MMAs).
// ---------------------------------------------------------------------------
#define SPP 68

#define KFS_OFF 0                    // 4096  : S-phase K frags (single buf)
#define VF_OFF  4096                 // 8192  : V frags (2 bufs x 4096)
#define KTF_OFF 12288                // 8192  : O-phase K frags (2 bufs)
#define QS_OFF  20480                // 8704  : Q staged (row-major)
#define PP_OFF  29184                // 17408 : P (2 bufs x 8704)
#define PP_SZ   8704
#define AL_OFF  46592                // 256   : alphas (2 bufs x 128)
#define LI_OFF  46848                // 128   : 1/l
#define SM_WORDS 46976

__global__ __launch_bounds__(512, 1) void attn_kernel(
    const int* __restrict__ mask, float* __restrict__ out_k, float* __restrict__ out_v)
{
    extern __shared__ unsigned sm[];
    unsigned* KFS = sm + KFS_OFF;
    unsigned* Qs  = sm + QS_OFF;
    float* alphas = (float*)(sm + AL_OFF);
    float* linv   = (float*)(sm + LI_OFF);

    const int tid  = threadIdx.x;
    const int warp = tid >> 5, lane = tid & 31;
    const int g = lane >> 2, tg = lane & 3;
    const int side = warp >> 3;          // 0: S-side   1: O-side
    const int wr   = warp & 7;
    const int w16  = wr * 16;
    const int q0 = blockIdx.x * 128;
    const int by = blockIdx.y;
    const int b  = by >> 4;
    const int h  = by & 15;

    // O-side role: warps 8-11 -> O_v, 12-15 -> O_k; 32 rows each
    const int oidx = warp - 8;           // 0..7 (valid when side==1)
    const int osel = oidx >> 2;          // 0: O_v, 1: O_k
    const int rg   = (oidx & 3) * 32;    // row base

    const float* Qg = g_Qh + ((size_t)by * LQ + q0) * DH;
    const float* Kg = g_Kh + (size_t)by * LK * DH;
    const float* Vg = g_Vh + (size_t)by * LK * DH;

    // ---- stage Q (all 512 threads, once) ----
#pragma unroll
    for (int rep = 0; rep < 4; rep++) {
        int idx = tid + 512 * rep;
        int r = idx >> 4, d4 = idx & 15;
        float4 qv = *(const float4*)(Qg + (size_t)r * DH + d4 * 4);
        *(uint4*)&Qs[r * SPP + d4 * 4] = make_uint4(
            f2tf(qv.x * 0.125f), f2tf(qv.y * 0.125f),
            f2tf(qv.z * 0.125f), f2tf(qv.w * 0.125f));
    }

    // acc[0..7]: S scratch s / O rows rg..rg+15 ; acc[8..15]: O rows rg+16..rg+31
    float acc[16][4];
#pragma unroll
    for (int nt = 0; nt < 16; nt++)
#pragma unroll
        for (int i = 0; i < 4; i++) acc[nt][i] = 0.f;
    float mi0 = -1e30f, mi1 = -1e30f, li0 = 0.f, li1 = 0.f;

    for (int t = 0; t <= NT; t++) {
        __syncthreads();   // publishes P[t-1]/alpha[t-1]; closes all prior-buf reads

        if (side == 0) {
            if (t < NT) {
                const int k0 = t * 64;
                // ---- stage K S-frags (256 threads, private to S-side) ----
#pragma unroll
                for (int rep = 0; rep < 4; rep++) {
                    int idx2 = tid + 256 * rep;
                    int key = idx2 >> 4, c4 = idx2 & 15;
                    float4 kv = *(const float4*)(Kg + (size_t)(k0 + key) * DH + c4 * 4);
                    int nt_ = key >> 3, gr = key & 7;
                    int kb = c4 >> 1, slot = c4 & 1;
                    unsigned vals[4] = {f2tf(kv.x), f2tf(kv.y), f2tf(kv.z), f2tf(kv.w)};
#pragma unroll
                    for (int j = 0; j < 4; j++) {
                        int rl = gr * 4 + j;
                        int chunk = (kb * 8 + nt_) * 32 + (rl ^ (((kb ^ nt_) & 15) << 1));
                        KFS[chunk * 2 + slot] = vals[j];
                    }
                }
                asm volatile("bar.sync 1, 256;" ::: "memory");

                // ---- S = Q K^T ----
#pragma unroll
                for (int nt = 0; nt < 8; nt++)
#pragma unroll
                    for (int i = 0; i < 4; i++) acc[nt][i] = 0.f;
#pragma unroll
                for (int kb = 0; kb < 8; kb++) {
                    unsigned qa[4];
                    int qb = (w16 + g) * SPP + kb * 8 + tg;
                    qa[0] = Qs[qb];
                    qa[1] = Qs[qb + 8 * SPP];
                    qa[2] = Qs[qb + 4];
                    qa[3] = Qs[qb + 8 * SPP + 4];
#pragma unroll
                    for (int nt = 0; nt < 8; nt++) {
                        int chunk = (kb * 8 + nt) * 32 + (lane ^ (((kb ^ nt) & 15) << 1));
                        uint2 bf = *(uint2*)&KFS[chunk * 2];
                        unsigned bfr[2] = {bf.x, bf.y};
                        mma_tf32(acc[nt], qa, bfr);
                    }
                }

                // ---- mask + online softmax ----
                const int qr0 = q0 + w16 + g;
                const size_t mrow0 = ((size_t)b * LQ + qr0) * LK + k0;
                const size_t mrow1 = mrow0 + 8 * (size_t)LK;
#pragma unroll
                for (int nt = 0; nt < 8; nt++) {
                    int col = nt * 8 + 2 * tg;
                    int2 m0v = *(const int2*)(mask + mrow0 + col);
                    int2 m1v = *(const int2*)(mask + mrow1 + col);
                    if (m0v.x == 0) acc[nt][0] = -1e30f;
                    if (m0v.y == 0) acc[nt][1] = -1e30f;
                    if (m1v.x == 0) acc[nt][2] = -1e30f;
                    if (m1v.y == 0) acc[nt][3] = -1e30f;
                }
                float mx0 = -1e30f, mx1 = -1e30f;
#pragma unroll
                for (int nt = 0; nt < 8; nt++) {
                    mx0 = fmaxf(mx0, fmaxf(acc[nt][0], acc[nt][1]));
                    mx1 = fmaxf(mx1, fmaxf(acc[nt][2], acc[nt][3]));
                }
                mx0 = fmaxf(mx0, __shfl_xor_sync(0xffffffffu, mx0, 1));
                mx0 = fmaxf(mx0, __shfl_xor_sync(0xffffffffu, mx0, 2));
                mx1 = fmaxf(mx1, __shfl_xor_sync(0xffffffffu, mx1, 1));
                mx1 = fmaxf(mx1, __shfl_xor_sync(0xffffffffu, mx1, 2));
                float mn0 = fmaxf(mi0, mx0), mn1 = fmaxf(mi1, mx1);
                float al0 = __expf(mi0 - mn0), al1 = __expf(mi1 - mn1);
                float rs0 = 0.f, rs1 = 0.f;
#pragma unroll
                for (int nt = 0; nt < 8; nt++) {
                    acc[nt][0] = __expf(acc[nt][0] - mn0); rs0 += acc[nt][0];
                    acc[nt][1] = __expf(acc[nt][1] - mn0); rs0 += acc[nt][1];
                    acc[nt][2] = __expf(acc[nt][2] - mn1); rs1 += acc[nt][2];
                    acc[nt][3] = __expf(acc[nt][3] - mn1); rs1 += acc[nt][3];
                }
                rs0 += __shfl_xor_sync(0xffffffffu, rs0, 1);
                rs0 += __shfl_xor_sync(0xffffffffu, rs0, 2);
                rs1 += __shfl_xor_sync(0xffffffffu, rs1, 1);
                rs1 += __shfl_xor_sync(0xffffffffu, rs1, 2);
                li0 = li0 * al0 + rs0; li1 = li1 * al1 + rs1;
                mi0 = mn0; mi1 = mn1;

                unsigned* Pb = sm + PP_OFF + (t & 1) * PP_SZ;
#pragma unroll
                for (int nt = 0; nt < 8; nt++) {
                    int base = (w16 + g) * SPP + nt * 8 + 2 * tg;
                    Pb[base]               = f2tf(acc[nt][0]);
                    Pb[base + 1]           = f2tf(acc[nt][1]);
                    Pb[base + 8 * SPP]     = f2tf(acc[nt][2]);
                    Pb[base + 8 * SPP + 1] = f2tf(acc[nt][3]);
                }
                if (tg == 0) {
                    alphas[(t & 1) * 128 + w16 + g]     = al0;
                    alphas[(t & 1) * 128 + w16 + 8 + g] = al1;
                }
            }
        } else {
            if (t < NT) {
                const int k0 = t * 64;
                unsigned* VFb  = sm + VF_OFF  + (t & 1) * 4096;
                unsigned* KTFb = sm + KTF_OFF + (t & 1) * 4096;
                const int ot = tid - 256;
#pragma unroll
                for (int rep = 0; rep < 4; rep++) {
                    int idx2 = ot + 256 * rep;
                    int key = idx2 >> 4, c4 = idx2 & 15;
                    float4 vv = *(const float4*)(Vg + (size_t)(k0 + key) * DH + c4 * 4);
                    float4 kv = *(const float4*)(Kg + (size_t)(k0 + key) * DH + c4 * 4);
                    int kbv = key >> 3, slot = (key & 7) >> 2, tgr = key & 3;
                    int nt_ = c4 >> 1;
                    unsigned va[4] = {f2tf(vv.x), f2tf(vv.y), f2tf(vv.z), f2tf(vv.w)};
                    unsigned ka[4] = {f2tf(kv.x), f2tf(kv.y), f2tf(kv.z), f2tf(kv.w)};
#pragma unroll
                    for (int j = 0; j < 4; j++) {
                        int gr = (c4 & 1) * 4 + j;
                        int rl = gr * 4 + tgr;
                        int chunk = (kbv * 8 + nt_) * 32 + (rl ^ (((kbv ^ nt_) & 15) << 1));
                        VFb[chunk * 2 + slot]  = va[j];
                        KTFb[chunk * 2 + slot] = ka[j];
                    }
                }
            }
            if (t > 0) {
                const int pb = (t - 1) & 1;
                unsigned* Pb = sm + PP_OFF + pb * PP_SZ;
                unsigned* Bf = sm + (osel ? KTF_OFF : VF_OFF) + pb * 4096;
                float a0 = alphas[pb * 128 + rg + g];
                float a1 = alphas[pb * 128 + rg + 8 + g];
                float a2 = alphas[pb * 128 + rg + 16 + g];
                float a3 = alphas[pb * 128 + rg + 24 + g];
#pragma unroll
                for (int nt = 0; nt < 8; nt++) {
                    acc[nt][0] *= a0;     acc[nt][1] *= a0;
                    acc[nt][2] *= a1;     acc[nt][3] *= a1;
                    acc[8 + nt][0] *= a2; acc[8 + nt][1] *= a2;
                    acc[8 + nt][2] *= a3; acc[8 + nt][3] *= a3;
                }
#pragma unroll
                for (int kb = 0; kb < 8; kb++) {
                    unsigned paA[4], paB[4];
                    int baseA = (rg + g) * SPP + kb * 8 + tg;
                    paA[0] = Pb[baseA];
                    paA[1] = Pb[baseA + 8 * SPP];
                    paA[2] = Pb[baseA + 4];
                    paA[3] = Pb[baseA + 8 * SPP + 4];
                    int baseB = (rg + 16 + g) * SPP + kb * 8 + tg;
                    paB[0] = Pb[baseB];
                    paB[1] = Pb[baseB + 8 * SPP];
                    paB[2] = Pb[baseB + 4];
                    paB[3] = Pb[baseB + 8 * SPP + 4];
#pragma unroll
                    for (int nt = 0; nt < 8; nt++) {
                        int chunk = (kb * 8 + nt) * 32 + (lane ^ (((kb ^ nt) & 15) << 1));
                        uint2 bf = *(uint2*)&Bf[chunk * 2];
                        unsigned bfr[2] = {bf.x, bf.y};
                        mma_tf32(acc[nt], paA, bfr);
                        mma_tf32(acc[8 + nt], paB, bfr);
                    }
                }
            }
        }
    }

    // ---- epilogue ----
    if (side == 0) {
        if (tg == 0) {
            linv[w16 + g]     = 1.f / li0;
            linv[w16 + 8 + g] = 1.f / li1;
        }
    }
    __syncthreads();
    if (side == 1) {
        float inv0 = linv[rg + g];
        float inv1 = linv[rg + 8 + g];
        float inv2 = linv[rg + 16 + g];
        float inv3 = linv[rg + 24 + g];
        float* outp = osel ? out_k : out_v;
        int r0 = q0 + rg + g;
#pragma unroll
        for (int nt = 0; nt < 8; nt++) {
            int d = nt * 8 + 2 * tg;
            size_t o0 = ((size_t)b * LQ + r0) * DM + h * DH + d;
            size_t o1 = ((size_t)b * LQ + r0 + 8) * DM + h * DH + d;
            size_t o2 = ((size_t)b * LQ + r0 + 16) * DM + h * DH + d;
            size_t o3 = ((size_t)b * LQ + r0 + 24) * DM + h * DH + d;
            *(float2*)(outp + o0) = make_float2(acc[nt][0] * inv0, acc[nt][1] * inv0);
            *(float2*)(outp + o1) = make_float2(acc[nt][2] * inv1, acc[nt][3] * inv1);
            *(float2*)(outp + o2) = make_float2(acc[8 + nt][0] * inv2, acc[8 + nt][1] * inv2);
            *(float2*)(outp + o3) = make_float2(acc[8 + nt][2] * inv3, acc[8 + nt][3] * inv3);
        }
    }
}

// ---------------------------------------------------------------------------
extern "C" void kernel_launch(void* const* d_in, const int* in_sizes, int n_in,
                              void* d_out, int out_size)
{
    const float* q    = (const float*)d_in[0];
    const float* k    = (const float*)d_in[1];
    const float* v    = (const float*)d_in[2];
    const int*   mask = (const int*)  d_in[3];
    const float* Wq   = (const float*)d_in[4];
    const float* bq   = (const float*)d_in[5];
    const float* Wk   = (const float*)d_in[6];
    const float* bk   = (const float*)d_in[7];
    const float* Wv   = (const float*)d_in[8];
    const float* bv   = (const float*)d_in[9];

    float* out_k = (float*)d_out;
    float* out_v = (float*)d_out + (size_t)BB * LQ * DM;

    static int smem_set = 0;
    if (!smem_set) {
        cudaFuncSetAttribute(attn_kernel, cudaFuncAttributeMaxDynamicSharedMemorySize,
                             SM_WORDS * (int)sizeof(unsigned));
        smem_set = 1;
    }

    dim3 pgrid(DM / 128, MTOT / 128, 3);
    proj_kernel<<<pgrid, 256>>>(q, k, v, Wq, bq, Wk, bk, Wv, bv);

    dim3 agrid(LQ / 128, BB * NH);
    attn_kernel<<<agrid, 512, SM_WORDS * (int)sizeof(unsigned)>>>(mask, out_k, out_v);
}